// round 1
// baseline (speedup 1.0000x reference)
#include <cuda_runtime.h>
#include <math.h>

#define BB 8
#define VV 6890
#define FF 13776
#define NP 4096
#define EPSF 1e-12f

// ---------------- device scratch (no allocations allowed) ----------------
__device__ float  g_cdf[BB * FF];          // per-face area, then normalized CDF
__device__ float4 g_fn [BB * FF];          // per-face unit normals
__device__ float4 g_pts[2 * BB * NP];      // sampled points, w = |p|^2
__device__ float4 g_nrm[2 * BB * NP];      // sampled normals
__device__ double g_acc[4];                // dist1, dist2, normloss, edge sums

// ---------------- kernels ----------------
__global__ void k_init() {
    if (threadIdx.x < 4) g_acc[threadIdx.x] = 0.0;
}

// Per (b,f): area, unit normal, and edge-loss partial sums.
__global__ void k_faces(const float* __restrict__ verts,
                        const int*   __restrict__ faces) {
    int id = blockIdx.x * blockDim.x + threadIdx.x;
    float esum = 0.f;
    if (id < BB * FF) {
        int b = id / FF, f = id % FF;
        int i0 = faces[f * 3 + 0];
        int i1 = faces[f * 3 + 1];
        int i2 = faces[f * 3 + 2];
        const float* vb = verts + (size_t)b * VV * 3;
        float ax = vb[i0*3+0], ay = vb[i0*3+1], az = vb[i0*3+2];
        float bx = vb[i1*3+0], by = vb[i1*3+1], bz = vb[i1*3+2];
        float cx = vb[i2*3+0], cy = vb[i2*3+1], cz = vb[i2*3+2];
        // u = v1-v0, w = v2-v0
        float ux = bx-ax, uy = by-ay, uz = bz-az;
        float wx = cx-ax, wy = cy-ay, wz = cz-az;
        float crx = uy*wz - uz*wy;
        float cry = uz*wx - ux*wz;
        float crz = ux*wy - uy*wx;
        float cn  = sqrtf(crx*crx + cry*cry + crz*crz);
        g_cdf[id] = 0.5f * cn;                       // area (pre-scan)
        float inv = 1.f / (cn + EPSF);
        g_fn[id]  = make_float4(crx*inv, cry*inv, crz*inv, 0.f);
        // edges: e01 = v0-v1 (= -u), e12 = v1-v2, e20 = v2-v0 (= w)
        float ex = bx-cx, ey = by-cy, ez = bz-cz;
        esum = (ux*ux + uy*uy + uz*uz)
             + (ex*ex + ey*ey + ez*ez)
             + (wx*wx + wy*wy + wz*wz);
    }
    __shared__ float sred[256];
    sred[threadIdx.x] = esum;
    __syncthreads();
    for (int s = 128; s > 0; s >>= 1) {
        if (threadIdx.x < s) sred[threadIdx.x] += sred[threadIdx.x + s];
        __syncthreads();
    }
    if (threadIdx.x == 0) atomicAdd(&g_acc[3], (double)sred[0]);
}

// Per-batch inclusive scan of areas -> normalized CDF. One block per batch.
__global__ void k_scan() {
    const int CH = (FF + 1023) / 1024;     // 14
    int b = blockIdx.x;
    int t = threadIdx.x;
    float* a = g_cdf + (size_t)b * FF;
    int beg = t * CH;
    int end = min(beg + CH, FF);
    float loc[CH];
    float s = 0.f;
    for (int i = beg; i < end; i++) { s += a[i]; loc[i - beg] = s; }
    __shared__ float ss[1024];
    ss[t] = s;
    __syncthreads();
    for (int off = 1; off < 1024; off <<= 1) {
        float v = (t >= off) ? ss[t - off] : 0.f;
        __syncthreads();
        ss[t] += v;
        __syncthreads();
    }
    float total = ss[1023];
    float excl  = ss[t] - s;
    float scale = 1.f / (total + EPSF);
    for (int i = beg; i < end; i++) a[i] = (excl + loc[i - beg]) * scale;
}

// Sample 2 point sets (set 0: rand_pred, set 1: rand_gt), both on predicted mesh.
__global__ void k_sample(const float* __restrict__ verts,
                         const int*   __restrict__ faces,
                         const float* __restrict__ rp,
                         const float* __restrict__ rg) {
    int id = blockIdx.x * blockDim.x + threadIdx.x;
    if (id >= 2 * BB * NP) return;
    int set = id / (BB * NP);
    int r   = id % (BB * NP);
    int b   = r / NP;
    const float* rnd = (set ? rg : rp) + (size_t)r * 3;
    float u  = rnd[0], r1 = rnd[1], r2 = rnd[2];
    const float* cdf = g_cdf + (size_t)b * FF;
    // searchsorted side='left': first i with cdf[i] >= u
    int lo = 0, hi = FF;
    while (lo < hi) {
        int mid = (lo + hi) >> 1;
        if (cdf[mid] < u) lo = mid + 1; else hi = mid;
    }
    int idx = min(lo, FF - 1);
    int i0 = faces[idx*3+0], i1 = faces[idx*3+1], i2 = faces[idx*3+2];
    const float* vb = verts + (size_t)b * VV * 3;
    float su = sqrtf(r1);
    float w0 = 1.f - su;
    float w1 = su * (1.f - r2);
    float w2 = su * r2;
    float x = w0*vb[i0*3+0] + w1*vb[i1*3+0] + w2*vb[i2*3+0];
    float y = w0*vb[i0*3+1] + w1*vb[i1*3+1] + w2*vb[i2*3+1];
    float z = w0*vb[i0*3+2] + w1*vb[i1*3+2] + w2*vb[i2*3+2];
    g_pts[set * BB * NP + r] = make_float4(x, y, z, x*x + y*y + z*z);
    g_nrm[set * BB * NP + r] = g_fn[(size_t)b * FF + idx];
}

// Chamfer pass. DIR=0: rows=set0(pc), min+argmin over set1(gc), + normal loss.
//               DIR=1: rows=set1(gc), min over set0(pc).
template <int DIR>
__global__ void k_cham() {
    const int TILE = 128;
    int b = blockIdx.y;
    int n = blockIdx.x * TILE + threadIdx.x;
    const float4* P = g_pts + (DIR ? 1 : 0) * BB * NP + (size_t)b * NP;
    const float4* Q = g_pts + (DIR ? 0 : 1) * BB * NP + (size_t)b * NP;
    float4 p = P[n];
    float best = 3.4e38f;
    int   bi   = 0;
    __shared__ float4 sq[TILE];
    for (int mt = 0; mt < NP; mt += TILE) {
        sq[threadIdx.x] = Q[mt + threadIdx.x];
        __syncthreads();
        #pragma unroll 8
        for (int j = 0; j < TILE; j++) {
            float4 q = sq[j];
            float dot = fmaf(p.x, q.x, fmaf(p.y, q.y, p.z * q.z));
            float d   = (p.w + q.w) - 2.f * dot;
            if (d < best) { best = d; bi = mt + j; }
        }
        __syncthreads();
    }
    float nloss = 0.f;
    if (DIR == 0) {
        float4 pn = g_nrm[0 * BB * NP + (size_t)b * NP + n];
        float4 qn = g_nrm[1 * BB * NP + (size_t)b * NP + bi];
        float d3 = pn.x*qn.x + pn.y*qn.y + pn.z*qn.z;
        nloss = 1.f - fabsf(d3);
    }
    __shared__ float rA[TILE];
    __shared__ float rB[TILE];
    rA[threadIdx.x] = best;
    rB[threadIdx.x] = nloss;
    __syncthreads();
    for (int s = TILE / 2; s > 0; s >>= 1) {
        if (threadIdx.x < s) {
            rA[threadIdx.x] += rA[threadIdx.x + s];
            rB[threadIdx.x] += rB[threadIdx.x + s];
        }
        __syncthreads();
    }
    if (threadIdx.x == 0) {
        atomicAdd(&g_acc[DIR], (double)rA[0]);
        if (DIR == 0) atomicAdd(&g_acc[2], (double)rB[0]);
    }
}

__global__ void k_final(float* out) {
    double invBN = 1.0 / (double)(BB * NP);
    double cham  = (g_acc[0] + g_acc[1]) * invBN;
    double nrm   = g_acc[2] * invBN;
    double edge  = g_acc[3] / (3.0 * (double)(BB * FF));
    out[0] = (float)(1.0 * cham + 0.1 * nrm + 0.5 * edge);
}

// ---------------- launch ----------------
extern "C" void kernel_launch(void* const* d_in, const int* in_sizes, int n_in,
                              void* d_out, int out_size) {
    const float* pv = (const float*)d_in[0];   // predicted_vertices (B,V,3)
    const int*   pf = (const int*)  d_in[1];   // predicted_faces (F,3)
    // d_in[2], d_in[3] (gt mesh) are unused by the reference computation
    const float* rp = (const float*)d_in[4];   // rand_pred (B,N,3)
    const float* rg = (const float*)d_in[5];   // rand_gt   (B,N,3)

    k_init<<<1, 32>>>();
    k_faces<<<(BB * FF + 255) / 256, 256>>>(pv, pf);
    k_scan<<<BB, 1024>>>();
    k_sample<<<(2 * BB * NP + 255) / 256, 256>>>(pv, pf, rp, rg);
    dim3 g(NP / 128, BB);
    k_cham<0><<<g, 128>>>();
    k_cham<1><<<g, 128>>>();
    k_final<<<1, 1>>>((float*)d_out);
}

// round 2
// speedup vs baseline: 1.1519x; 1.1519x over previous
#include <cuda_runtime.h>
#include <math.h>

#define BB 8
#define VV 6890
#define FF 13776
#define NP 4096
#define EPSF 1e-12f
#define NC ((FF + 15) / 16)          // 861 coarse CDF entries

// ---------------- device scratch (no allocations allowed) ----------------
__device__ float  g_cdf[BB * FF];                 // per-face area -> normalized CDF
__device__ float4 g_fn [BB * FF];                 // per-face unit normals
__device__ float4 g_pts[2 * BB * NP];             // sampled points, w = |p|^2
__device__ float4 g_nrm[2 * BB * NP];             // sampled normals
__device__ unsigned long long g_key[2 * BB * NP]; // per-row min keys (dist|idx)
__device__ double g_acc[4];                       // dist1, dist2, normloss, edge

// ordered mapping: monotone increasing float -> uint
__device__ __forceinline__ unsigned int ford(float f) {
    unsigned int b = __float_as_uint(f);
    return (b & 0x80000000u) ? ~b : (b | 0x80000000u);
}
__device__ __forceinline__ float iford(unsigned int u) {
    unsigned int b = (u & 0x80000000u) ? (u & 0x7FFFFFFFu) : ~u;
    return __uint_as_float(b);
}

// ---------------- kernels ----------------
__global__ void k_init() {
    int i = blockIdx.x * blockDim.x + threadIdx.x;
    if (i < 2 * BB * NP) g_key[i] = 0xFFFFFFFFFFFFFFFFull;
    if (i < 4) g_acc[i] = 0.0;
}

// Per (b,f): area, unit normal, and edge-loss partial sums.
__global__ void k_faces(const float* __restrict__ verts,
                        const int*   __restrict__ faces) {
    int id = blockIdx.x * blockDim.x + threadIdx.x;
    float esum = 0.f;
    if (id < BB * FF) {
        int b = id / FF, f = id % FF;
        int i0 = faces[f * 3 + 0];
        int i1 = faces[f * 3 + 1];
        int i2 = faces[f * 3 + 2];
        const float* vb = verts + (size_t)b * VV * 3;
        float ax = vb[i0*3+0], ay = vb[i0*3+1], az = vb[i0*3+2];
        float bx = vb[i1*3+0], by = vb[i1*3+1], bz = vb[i1*3+2];
        float cx = vb[i2*3+0], cy = vb[i2*3+1], cz = vb[i2*3+2];
        float ux = bx-ax, uy = by-ay, uz = bz-az;   // v1-v0
        float wx = cx-ax, wy = cy-ay, wz = cz-az;   // v2-v0
        float crx = uy*wz - uz*wy;
        float cry = uz*wx - ux*wz;
        float crz = ux*wy - uy*wx;
        float cn  = sqrtf(crx*crx + cry*cry + crz*crz);
        g_cdf[id] = 0.5f * cn;
        float inv = 1.f / (cn + EPSF);
        g_fn[id]  = make_float4(crx*inv, cry*inv, crz*inv, 0.f);
        float ex = bx-cx, ey = by-cy, ez = bz-cz;   // v1-v2
        esum = (ux*ux + uy*uy + uz*uz)
             + (ex*ex + ey*ey + ez*ez)
             + (wx*wx + wy*wy + wz*wz);
    }
    __shared__ float sred[256];
    sred[threadIdx.x] = esum;
    __syncthreads();
    for (int s = 128; s > 0; s >>= 1) {
        if (threadIdx.x < s) sred[threadIdx.x] += sred[threadIdx.x + s];
        __syncthreads();
    }
    if (threadIdx.x == 0) atomicAdd(&g_acc[3], (double)sred[0]);
}

// Per-batch inclusive scan of areas -> normalized CDF. One block per batch.
__global__ void k_scan() {
    const int CH = (FF + 1023) / 1024;     // 14
    int b = blockIdx.x;
    int t = threadIdx.x;
    float* a = g_cdf + (size_t)b * FF;
    int beg = t * CH;
    int end = min(beg + CH, FF);
    float loc[CH];
    float s = 0.f;
    for (int i = beg; i < end; i++) { s += a[i]; loc[i - beg] = s; }
    __shared__ float ss[1024];
    ss[t] = s;
    __syncthreads();
    for (int off = 1; off < 1024; off <<= 1) {
        float v = (t >= off) ? ss[t - off] : 0.f;
        __syncthreads();
        ss[t] += v;
        __syncthreads();
    }
    float total = ss[1023];
    float excl  = ss[t] - s;
    float scale = 1.f / (total + EPSF);
    for (int i = beg; i < end; i++) a[i] = (excl + loc[i - beg]) * scale;
}

// Sample points. grid (4 chunks, 8 batches, 2 sets), block 1024.
// Two-level CDF search: coarse stride-16 table in shared, fine in global (L2).
__global__ void k_sample(const float* __restrict__ verts,
                         const int*   __restrict__ faces,
                         const float* __restrict__ rp,
                         const float* __restrict__ rg) {
    int set = blockIdx.z;
    int b   = blockIdx.y;
    int n   = blockIdx.x * 1024 + threadIdx.x;
    const float* cdf = g_cdf + (size_t)b * FF;
    __shared__ float sc[NC];
    for (int i = threadIdx.x; i < NC; i += 1024)
        sc[i] = cdf[i * 16 + 15];
    __syncthreads();

    const float* rnd = (set ? rg : rp) + ((size_t)b * NP + n) * 3;
    float u = rnd[0], r1 = rnd[1], r2 = rnd[2];

    // coarse: first k with sc[k] >= u
    int lo = 0, hi = NC;
    while (lo < hi) {
        int m = (lo + hi) >> 1;
        if (sc[m] < u) lo = m + 1; else hi = m;
    }
    int idx;
    if (lo == NC) {
        idx = FF - 1;                      // u beyond cdf end -> clip
    } else {
        int l = lo * 16, h = l + 16;       // crossing guaranteed inside
        while (l < h) {
            int m = (l + h) >> 1;
            if (cdf[m] < u) l = m + 1; else h = m;
        }
        idx = min(l, FF - 1);
    }
    int i0 = faces[idx*3+0], i1 = faces[idx*3+1], i2 = faces[idx*3+2];
    const float* vb = verts + (size_t)b * VV * 3;
    float su = sqrtf(r1);
    float w0 = 1.f - su;
    float w1 = su * (1.f - r2);
    float w2 = su * r2;
    float x = w0*vb[i0*3+0] + w1*vb[i1*3+0] + w2*vb[i2*3+0];
    float y = w0*vb[i0*3+1] + w1*vb[i1*3+1] + w2*vb[i2*3+1];
    float z = w0*vb[i0*3+2] + w1*vb[i1*3+2] + w2*vb[i2*3+2];
    int out = set * BB * NP + b * NP + n;
    g_pts[out] = make_float4(x, y, z, x*x + y*y + z*z);
    g_nrm[out] = g_fn[(size_t)b * FF + idx];
}

// Chamfer pass, register-tiled: 4 rows/thread, column-chunked grid.
// DIR=0: rows=set0(pc), min+argmin over set1(gc).
// DIR=1: rows=set1(gc), min over set0(pc).
// d' = q.w - 2*p.q  (p.w added back in k_post; doesn't affect argmin)
template <int DIR>
__global__ void k_cham() {
    const int QT = 256, RPT = 4, COLS = 512;
    int b    = blockIdx.z;
    int row0 = blockIdx.x * (256 * RPT) + threadIdx.x * RPT;   // within batch
    int c0   = blockIdx.y * COLS;
    const float4* P = g_pts + (DIR ? BB*NP : 0) + (size_t)b * NP;
    const float4* Q = g_pts + (DIR ? 0 : BB*NP) + (size_t)b * NP;

    float px2[RPT], py2[RPT], pz2[RPT], best[RPT];
    int besti[RPT];
    #pragma unroll
    for (int r = 0; r < RPT; r++) {
        float4 p = P[row0 + r];
        px2[r] = -2.f * p.x;
        py2[r] = -2.f * p.y;
        pz2[r] = -2.f * p.z;
        best[r] = 3.4e38f;
        besti[r] = 0;
    }

    __shared__ float4 sq[QT];
    for (int t = 0; t < COLS; t += QT) {
        sq[threadIdx.x] = Q[c0 + t + threadIdx.x];
        __syncthreads();
        #pragma unroll 4
        for (int j = 0; j < QT; j++) {
            float4 q = sq[j];
            #pragma unroll
            for (int r = 0; r < RPT; r++) {
                float d = fmaf(pz2[r], q.z,
                          fmaf(py2[r], q.y,
                          fmaf(px2[r], q.x, q.w)));
                if (DIR == 0) {
                    if (d < best[r]) besti[r] = c0 + t + j;
                    best[r] = fminf(best[r], d);
                } else {
                    best[r] = fminf(best[r], d);
                }
            }
        }
        __syncthreads();
    }
    #pragma unroll
    for (int r = 0; r < RPT; r++) {
        unsigned long long key =
            ((unsigned long long)ford(best[r]) << 32) | (unsigned int)besti[r];
        atomicMin(&g_key[DIR * BB * NP + (size_t)b * NP + row0 + r], key);
    }
}

// Decode per-row min keys, accumulate chamfer sums + normal loss.
__global__ void k_post() {
    int i   = blockIdx.x * 256 + threadIdx.x;   // 0 .. 2*BB*NP
    int dir = i / (BB * NP);                    // uniform per block (32768%256==0)
    int r   = i % (BB * NP);
    unsigned long long key = g_key[i];
    float d = iford((unsigned int)(key >> 32)) + g_pts[i].w;
    float nl = 0.f;
    if (dir == 0) {
        int idx = (int)(key & 0xFFFFFFFFu);
        int b = r / NP;
        float4 pn = g_nrm[r];
        float4 qn = g_nrm[BB * NP + (size_t)b * NP + idx];
        nl = 1.f - fabsf(pn.x*qn.x + pn.y*qn.y + pn.z*qn.z);
    }
    __shared__ float rA[256];
    __shared__ float rB[256];
    rA[threadIdx.x] = d;
    rB[threadIdx.x] = nl;
    __syncthreads();
    for (int s = 128; s > 0; s >>= 1) {
        if (threadIdx.x < s) {
            rA[threadIdx.x] += rA[threadIdx.x + s];
            rB[threadIdx.x] += rB[threadIdx.x + s];
        }
        __syncthreads();
    }
    if (threadIdx.x == 0) {
        atomicAdd(&g_acc[dir], (double)rA[0]);
        if (dir == 0) atomicAdd(&g_acc[2], (double)rB[0]);
    }
}

__global__ void k_final(float* out) {
    double invBN = 1.0 / (double)(BB * NP);
    double cham  = (g_acc[0] + g_acc[1]) * invBN;
    double nrm   = g_acc[2] * invBN;
    double edge  = g_acc[3] / (3.0 * (double)(BB * FF));
    out[0] = (float)(1.0 * cham + 0.1 * nrm + 0.5 * edge);
}

// ---------------- launch ----------------
extern "C" void kernel_launch(void* const* d_in, const int* in_sizes, int n_in,
                              void* d_out, int out_size) {
    const float* pv = (const float*)d_in[0];   // predicted_vertices (B,V,3)
    const int*   pf = (const int*)  d_in[1];   // predicted_faces (F,3)
    // d_in[2], d_in[3] (gt mesh) are unused by the reference computation
    const float* rp = (const float*)d_in[4];   // rand_pred (B,N,3)
    const float* rg = (const float*)d_in[5];   // rand_gt   (B,N,3)

    k_init<<<(2 * BB * NP + 255) / 256, 256>>>();
    k_faces<<<(BB * FF + 255) / 256, 256>>>(pv, pf);
    k_scan<<<BB, 1024>>>();
    k_sample<<<dim3(4, BB, 2), 1024>>>(pv, pf, rp, rg);
    dim3 g(NP / (256 * 4), NP / 512, BB);      // (4, 8, 8) = 256 blocks
    k_cham<0><<<g, 256>>>();
    k_cham<1><<<g, 256>>>();
    k_post<<<2 * BB * NP / 256, 256>>>();
    k_final<<<1, 1>>>((float*)d_out);
}

// round 3
// speedup vs baseline: 1.8322x; 1.5906x over previous
#include <cuda_runtime.h>
#include <math.h>

#define BB 8
#define VV 6890
#define FF 13776
#define NP 4096
#define EPSF 1e-12f
#define NC ((FF + 15) / 16)          // 861 coarse CDF entries
#define NFB ((BB * FF + 255) / 256)  // 431 k_faces blocks
#define RBLK 32                      // row blocks per batch (4096/128)

// ---------------- device scratch (no allocations allowed) ----------------
__device__ float        g_cdf[BB * FF];            // per-face area -> CDF
__device__ float4       g_fn [BB * FF];            // per-face unit normals
__device__ float4       g_pts[2 * BB * NP];        // sampled points, w=|p|^2
__device__ float4       g_nrm[2 * BB * NP];        // sampled normals
__device__ unsigned int g_rowm[BB * NP];           // per-row mangled min (bits)
__device__ float        g_colp[BB * RBLK * NP];    // col-min partials (4MB)
__device__ float        g_edge[NFB];               // edge-loss block partials
__device__ float        g_part[512];               // k_post block partials (d,n)

// ---------------- kernels ----------------

// Per (b,f): area, unit normal, edge partial per block.
__global__ void k_faces(const float* __restrict__ verts,
                        const int*   __restrict__ faces) {
    int id = blockIdx.x * blockDim.x + threadIdx.x;
    float esum = 0.f;
    if (id < BB * FF) {
        int b = id / FF, f = id % FF;
        int i0 = faces[f * 3 + 0];
        int i1 = faces[f * 3 + 1];
        int i2 = faces[f * 3 + 2];
        const float* vb = verts + (size_t)b * VV * 3;
        float ax = vb[i0*3+0], ay = vb[i0*3+1], az = vb[i0*3+2];
        float bx = vb[i1*3+0], by = vb[i1*3+1], bz = vb[i1*3+2];
        float cx = vb[i2*3+0], cy = vb[i2*3+1], cz = vb[i2*3+2];
        float ux = bx-ax, uy = by-ay, uz = bz-az;   // v1-v0
        float wx = cx-ax, wy = cy-ay, wz = cz-az;   // v2-v0
        float crx = uy*wz - uz*wy;
        float cry = uz*wx - ux*wz;
        float crz = ux*wy - uy*wx;
        float cn  = sqrtf(crx*crx + cry*cry + crz*crz);
        g_cdf[id] = 0.5f * cn;
        float inv = 1.f / (cn + EPSF);
        g_fn[id]  = make_float4(crx*inv, cry*inv, crz*inv, 0.f);
        float ex = bx-cx, ey = by-cy, ez = bz-cz;   // v1-v2
        esum = (ux*ux + uy*uy + uz*uz)
             + (ex*ex + ey*ey + ez*ez)
             + (wx*wx + wy*wy + wz*wz);
    }
    __shared__ float sred[256];
    sred[threadIdx.x] = esum;
    __syncthreads();
    for (int s = 128; s > 0; s >>= 1) {
        if (threadIdx.x < s) sred[threadIdx.x] += sred[threadIdx.x + s];
        __syncthreads();
    }
    if (threadIdx.x == 0) g_edge[blockIdx.x] = sred[0];
}

// Per-batch inclusive scan of areas -> normalized CDF. One block per batch.
__global__ void k_scan() {
    const int CH = (FF + 1023) / 1024;     // 14
    int b = blockIdx.x;
    int t = threadIdx.x;
    float* a = g_cdf + (size_t)b * FF;
    int beg = t * CH;
    int end = min(beg + CH, FF);
    float loc[CH];
    float s = 0.f;
    for (int i = beg; i < end; i++) { s += a[i]; loc[i - beg] = s; }
    __shared__ float ss[1024];
    ss[t] = s;
    __syncthreads();
    for (int off = 1; off < 1024; off <<= 1) {
        float v = (t >= off) ? ss[t - off] : 0.f;
        __syncthreads();
        ss[t] += v;
        __syncthreads();
    }
    float total = ss[1023];
    float excl  = ss[t] - s;
    float scale = 1.f / (total + EPSF);
    for (int i = beg; i < end; i++) a[i] = (excl + loc[i - beg]) * scale;
}

// Sample points. grid (16 chunks, 8 batches, 2 sets), block 256.
__global__ void k_sample(const float* __restrict__ verts,
                         const int*   __restrict__ faces,
                         const float* __restrict__ rp,
                         const float* __restrict__ rg) {
    int set = blockIdx.z;
    int b   = blockIdx.y;
    int n   = blockIdx.x * 256 + threadIdx.x;
    const float* cdf = g_cdf + (size_t)b * FF;
    __shared__ float sc[NC];
    for (int i = threadIdx.x; i < NC; i += 256)
        sc[i] = cdf[i * 16 + 15];
    __syncthreads();

    const float* rnd = (set ? rg : rp) + ((size_t)b * NP + n) * 3;
    float u = rnd[0], r1 = rnd[1], r2 = rnd[2];

    // coarse: first k with sc[k] >= u
    int lo = 0, hi = NC;
    while (lo < hi) {
        int m = (lo + hi) >> 1;
        if (sc[m] < u) lo = m + 1; else hi = m;
    }
    int idx;
    if (lo == NC) {
        idx = FF - 1;
    } else {
        int l = lo * 16, h = l + 16;
        while (l < h) {
            int m = (l + h) >> 1;
            if (cdf[m] < u) l = m + 1; else h = m;
        }
        idx = min(l, FF - 1);
    }
    int i0 = faces[idx*3+0], i1 = faces[idx*3+1], i2 = faces[idx*3+2];
    const float* vb = verts + (size_t)b * VV * 3;
    float su = sqrtf(r1);
    float w0 = 1.f - su;
    float w1 = su * (1.f - r2);
    float w2 = su * r2;
    float x = w0*vb[i0*3+0] + w1*vb[i1*3+0] + w2*vb[i2*3+0];
    float y = w0*vb[i0*3+1] + w1*vb[i1*3+1] + w2*vb[i2*3+1];
    float z = w0*vb[i0*3+2] + w1*vb[i1*3+2] + w2*vb[i2*3+2];
    int out = set * BB * NP + b * NP + n;
    g_pts[out] = make_float4(x, y, z, x*x + y*y + z*z);
    g_nrm[out] = g_fn[(size_t)b * FF + idx];
}

// Fused chamfer: one pass over d[b,:,:], updates row-min (mangled argmin)
// and col-min (exact value) simultaneously.
// grid (RBLK, BB), block 256: tx = tid>>4 (col group), ty = tid&15 (row group).
__global__ void __launch_bounds__(256) k_cham() {
    const int b  = blockIdx.y;
    const int rb = blockIdx.x * 128;
    const int tid = threadIdx.x;
    const int tx = tid >> 4;
    const int ty = tid & 15;
    const float4* __restrict__ P = g_pts + (size_t)b * NP;
    const float4* __restrict__ Q = g_pts + BB * NP + (size_t)b * NP;

    __shared__ float4 sq[128];
    __shared__ unsigned int srow[128][17];

    float px2[8], py2[8], pz2[8], pw[8], rowb[8];
    #pragma unroll
    for (int i = 0; i < 8; i++) {
        float4 p = P[rb + ty * 8 + i];
        px2[i] = -2.f * p.x;
        py2[i] = -2.f * p.y;
        pz2[i] = -2.f * p.z;
        pw[i]  = p.w;
        rowb[i] = __int_as_float(0x7F800000);   // +inf
    }

    for (int ct = 0; ct < NP; ct += 128) {
        if (tid < 128) sq[tid] = Q[ct + tid];
        __syncthreads();
        float colb[8];
        #pragma unroll
        for (int jj = 0; jj < 8; jj++) colb[jj] = __int_as_float(0x7F800000);
        #pragma unroll
        for (int jj = 0; jj < 8; jj++) {
            float4 q = sq[tx * 8 + jj];
            unsigned int col = ct + tx * 8 + jj;
            #pragma unroll
            for (int i = 0; i < 8; i++) {
                float d = fmaf(px2[i], q.x,
                          fmaf(py2[i], q.y,
                          fmaf(pz2[i], q.z, q.w))) + pw[i];
                unsigned int m = (__float_as_uint(d) & 0xFFFFF000u) | col;
                rowb[i]  = fminf(rowb[i], __uint_as_float(m));
                colb[jj] = fminf(colb[jj], d);
            }
        }
        // reduce col mins across ty (16 consecutive lanes = half-warp)
        #pragma unroll
        for (int jj = 0; jj < 8; jj++) {
            float v = colb[jj];
            v = fminf(v, __shfl_xor_sync(0xffffffffu, v, 8, 16));
            v = fminf(v, __shfl_xor_sync(0xffffffffu, v, 4, 16));
            v = fminf(v, __shfl_xor_sync(0xffffffffu, v, 2, 16));
            v = fminf(v, __shfl_xor_sync(0xffffffffu, v, 1, 16));
            colb[jj] = v;
        }
        if (ty == 0) {
            int base = ((b * RBLK + blockIdx.x) << 12) + ct + tx * 8;
            *(float4*)&g_colp[base]     = make_float4(colb[0], colb[1], colb[2], colb[3]);
            *(float4*)&g_colp[base + 4] = make_float4(colb[4], colb[5], colb[6], colb[7]);
        }
        __syncthreads();
    }

    // reduce row mins across tx (once per block), then plain store
    #pragma unroll
    for (int i = 0; i < 8; i++) srow[ty * 8 + i][tx] = __float_as_uint(rowb[i]);
    __syncthreads();
    if (tid < 128) {
        float best = __uint_as_float(srow[tid][0]);
        #pragma unroll
        for (int k = 1; k < 16; k++)
            best = fminf(best, __uint_as_float(srow[tid][k]));
        g_rowm[(size_t)b * NP + rb + tid] = __float_as_uint(best);
    }
}

// Decode row mins (recompute exact distance + normal loss from argmin),
// reduce col partials; per-block partial sums to g_part (no atomics).
__global__ void k_post() {
    int gid = blockIdx.x * 256 + threadIdx.x;   // 0..65535
    float sd = 0.f, sn = 0.f;
    if (gid < BB * NP) {                        // rows -> dist1 + normals
        int b = gid >> 12;
        unsigned int m = g_rowm[gid];
        int col = m & 0xFFF;
        int qi  = BB * NP + (b << 12) + col;
        float4 p = g_pts[gid];
        float4 q = g_pts[qi];
        sd = p.w + q.w - 2.f * (p.x*q.x + p.y*q.y + p.z*q.z);
        float4 pn = g_nrm[gid];
        float4 qn = g_nrm[qi];
        sn = 1.f - fabsf(pn.x*qn.x + pn.y*qn.y + pn.z*qn.z);
    } else {                                    // cols -> dist2
        int c = gid - BB * NP;
        int b = c >> 12, col = c & 4095;
        float best = __int_as_float(0x7F800000);
        #pragma unroll 8
        for (int k = 0; k < RBLK; k++)
            best = fminf(best, g_colp[((b * RBLK + k) << 12) + col]);
        sd = best;
    }
    __shared__ float rA[256];
    __shared__ float rB[256];
    rA[threadIdx.x] = sd;
    rB[threadIdx.x] = sn;
    __syncthreads();
    for (int s = 128; s > 0; s >>= 1) {
        if (threadIdx.x < s) {
            rA[threadIdx.x] += rA[threadIdx.x + s];
            rB[threadIdx.x] += rB[threadIdx.x + s];
        }
        __syncthreads();
    }
    if (threadIdx.x == 0) {
        g_part[blockIdx.x * 2 + 0] = rA[0];
        g_part[blockIdx.x * 2 + 1] = rB[0];
    }
}

// Final: sum 256 block partials + 431 edge partials, compose loss.
__global__ void k_final(float* out) {
    int t = threadIdx.x;   // 256 threads
    float sd = g_part[t * 2 + 0];
    float sn = g_part[t * 2 + 1];
    float se = (t < NFB ? g_edge[t] : 0.f) + (t + 256 < NFB ? g_edge[t + 256] : 0.f);
    __shared__ float rA[256], rB[256], rC[256];
    rA[t] = sd; rB[t] = sn; rC[t] = se;
    __syncthreads();
    for (int s = 128; s > 0; s >>= 1) {
        if (t < s) { rA[t] += rA[t+s]; rB[t] += rB[t+s]; rC[t] += rC[t+s]; }
        __syncthreads();
    }
    if (t == 0) {
        double invBN = 1.0 / (double)(BB * NP);
        double cham  = (double)rA[0] * invBN;
        double nrm   = (double)rB[0] * invBN;
        double edge  = (double)rC[0] / (3.0 * (double)(BB * FF));
        out[0] = (float)(1.0 * cham + 0.1 * nrm + 0.5 * edge);
    }
}

// ---------------- launch ----------------
extern "C" void kernel_launch(void* const* d_in, const int* in_sizes, int n_in,
                              void* d_out, int out_size) {
    const float* pv = (const float*)d_in[0];   // predicted_vertices (B,V,3)
    const int*   pf = (const int*)  d_in[1];   // predicted_faces (F,3)
    // d_in[2], d_in[3] (gt mesh) unused by the reference computation
    const float* rp = (const float*)d_in[4];   // rand_pred (B,N,3)
    const float* rg = (const float*)d_in[5];   // rand_gt   (B,N,3)

    k_faces<<<NFB, 256>>>(pv, pf);
    k_scan<<<BB, 1024>>>();
    k_sample<<<dim3(16, BB, 2), 256>>>(pv, pf, rp, rg);
    k_cham<<<dim3(RBLK, BB), 256>>>();
    k_post<<<2 * BB * NP / 256, 256>>>();
    k_final<<<1, 256>>>((float*)d_out);
}